// round 6
// baseline (speedup 1.0000x reference)
#include <cuda_runtime.h>

// QConv2d: new_rho[b] = V * rho[b] * V^T  with V = kron(uc[:,2:4], ux, uy) (256x128)
// (channel insertion is a pure index shift by 128: new_idx = x + 128)
//
// Factorized Kronecker application (uy -> ux -> uc2) = 2560 FMA per 128-vector
// instead of 32768, done entirely in shared memory, one CTA per batch.

#define QK   128          // c_in  * d*d
#define PK   256          // c_out * d*d
#define WSTR 132          // W row stride (floats): 16B-aligned rows, phase-conflict-free
#define SSTR 128          // rho column-major-access stride
#define ASTR 132          // A2 scratch row stride

static constexpr int S_OFF      = 256 * WSTR;            // W is [256][WSTR] at offset 0
static constexpr int UY_OFF     = S_OFF + 128 * ASTR;    // scratch: max(rho 128*128, A2 128*132)
static constexpr int UX_OFF     = UY_OFF + 64;
static constexpr int UC_OFF     = UX_OFF + 64;
static constexpr int SMEM_FLOATS = UC_OFF + 8;
static constexpr int SMEM_BYTES  = SMEM_FLOATS * 4;      // 203,296 B < 227 KB

__global__ void __launch_bounds__(256, 1)
qconv_kernel(const float* __restrict__ rho_g,
             const float* __restrict__ ux_g,
             const float* __restrict__ uy_g,
             const float* __restrict__ uc_g,
             float* __restrict__ out_g)
{
    extern __shared__ float sm[];
    float* __restrict__ Wsh = sm;             // [256][WSTR]
    float* __restrict__ Ssh = sm + S_OFF;     // rho [128][SSTR], later A2 [128][ASTR]
    float* __restrict__ Uy  = sm + UY_OFF;    // [8][8]
    float* __restrict__ Ux  = sm + UX_OFF;    // [8][8]
    float* __restrict__ Uc2 = sm + UC_OFF;    // [4][2] : uc[g][2+f]

    const int tid = threadIdx.x;
    const int b   = blockIdx.x;

    // Load the small transform matrices.
    if (tid < 64) {
        Uy[tid] = uy_g[tid];
        Ux[tid] = ux_g[tid];
    } else if (tid < 72) {
        int t = tid - 64;                    // t = g*2 + f
        Uc2[t] = uc_g[(t >> 1) * 4 + 2 + (t & 1)];
    }

    // Load rho[b] (128x128 fp32 = 16 KB floats) coalesced as float4.
    {
        const float4* __restrict__ src =
            reinterpret_cast<const float4*>(rho_g) + (size_t)b * (QK * QK / 4);
        float4* dst = reinterpret_cast<float4*>(Ssh);
        #pragma unroll
        for (int i = 0; i < 16; i++)
            dst[tid + i * 256] = src[tid + i * 256];
    }
    __syncthreads();

    const int fh     = tid >> 7;      // f' half (0/1)
    const int lane_r = tid & 127;     // column index r

    // ---------------- Stage 1a: per-column uy then ux (2 threads / column) ------------
    // out half written back in place over the consumed rho half.
    {
        float* col = Ssh + (fh * 64) * SSTR + lane_r;   // col[c*SSTR]

        float a1[64];
        #pragma unroll
        for (int i = 0; i < 8; i++) {
            float v[8];
            #pragma unroll
            for (int j = 0; j < 8; j++)
                v[j] = col[(i * 8 + j) * SSTR];
            #pragma unroll
            for (int l = 0; l < 8; l++) {
                float acc = Uy[l * 8] * v[0];
                #pragma unroll
                for (int j = 1; j < 8; j++)
                    acc = fmaf(Uy[l * 8 + j], v[j], acc);
                a1[i * 8 + l] = acc;
            }
        }
        #pragma unroll
        for (int k = 0; k < 8; k++) {
            float u[8];
            #pragma unroll
            for (int i = 0; i < 8; i++) u[i] = Ux[k * 8 + i];
            #pragma unroll
            for (int l = 0; l < 8; l++) {
                float acc = u[0] * a1[l];
                #pragma unroll
                for (int i = 1; i < 8; i++)
                    acc = fmaf(u[i], a1[i * 8 + l], acc);
                col[(k * 8 + l) * SSTR] = acc;           // overwrite own consumed half
            }
        }
    }
    __syncthreads();

    // ---------------- Stage 1b: uc2 combine -> W[(g,k,l)][r] ---------------------------
    {
        const float c00 = Uc2[0], c01 = Uc2[1], c10 = Uc2[2], c11 = Uc2[3];
        const float c20 = Uc2[4], c21 = Uc2[5], c30 = Uc2[6], c31 = Uc2[7];
        #pragma unroll
        for (int it = 0; it < 32; it++) {
            int pos = tid + it * 256;          // 0..8191 over (kl, r)
            int r   = pos & 127;
            int kl  = pos >> 7;
            float x0 = Ssh[kl * SSTR + r];
            float x1 = Ssh[(64 + kl) * SSTR + r];
            Wsh[(0 * 64 + kl) * WSTR + r] = fmaf(c01, x1, c00 * x0);
            Wsh[(1 * 64 + kl) * WSTR + r] = fmaf(c11, x1, c10 * x0);
            Wsh[(2 * 64 + kl) * WSTR + r] = fmaf(c21, x1, c20 * x0);
            Wsh[(3 * 64 + kl) * WSTR + r] = fmaf(c31, x1, c30 * x0);
        }
    }
    __syncthreads();

    // ---------------- Stage 2: per-row transform of W, 2 chunks of 128 rows ------------
    float* __restrict__ Y = out_g + (size_t)b * (PK * PK);

    #pragma unroll 1
    for (int chunk = 0; chunk < 2; chunk++) {
        const int pl = lane_r;                 // local row 0..127
        const int p  = chunk * 128 + pl;

        // uy stage: a1[i][l] from W row half
        float a1[64];
        {
            const float* wrow = Wsh + p * WSTR + fh * 64;
            #pragma unroll
            for (int i = 0; i < 8; i++) {
                float4 wa = *reinterpret_cast<const float4*>(wrow + i * 8);
                float4 wb = *reinterpret_cast<const float4*>(wrow + i * 8 + 4);
                float v[8] = {wa.x, wa.y, wa.z, wa.w, wb.x, wb.y, wb.z, wb.w};
                #pragma unroll
                for (int l = 0; l < 8; l++) {
                    float acc = Uy[l * 8] * v[0];
                    #pragma unroll
                    for (int j = 1; j < 8; j++)
                        acc = fmaf(Uy[l * 8 + j], v[j], acc);
                    a1[i * 8 + l] = acc;
                }
            }
        }
        // ux stage: write A2[pl][fh][k*8+l] (row-at-a-time, float4 STS)
        {
            float* arow = Ssh + pl * ASTR + fh * 64;
            #pragma unroll
            for (int k = 0; k < 8; k++) {
                float u[8];
                #pragma unroll
                for (int i = 0; i < 8; i++) u[i] = Ux[k * 8 + i];
                float o[8];
                #pragma unroll
                for (int l = 0; l < 8; l++) {
                    float acc = u[0] * a1[l];
                    #pragma unroll
                    for (int i = 1; i < 8; i++)
                        acc = fmaf(u[i], a1[i * 8 + l], acc);
                    o[l] = acc;
                }
                float4 o0 = make_float4(o[0], o[1], o[2], o[3]);
                float4 o1 = make_float4(o[4], o[5], o[6], o[7]);
                *reinterpret_cast<float4*>(arow + k * 8)     = o0;
                *reinterpret_cast<float4*>(arow + k * 8 + 4) = o1;
            }
        }
        __syncthreads();

        // uc2 combine fused with coalesced float4 global stores
        {
            #pragma unroll
            for (int it = 0; it < 32; it++) {
                int idx    = tid + it * 256;      // 0..8191 float4 slots (128 rows x 64)
                int plocal = idx >> 6;            // 0..127
                int s4     = idx & 63;            // float4 index within output row
                int g      = s4 >> 4;
                int kl     = (s4 & 15) * 4;
                float4 x0 = *reinterpret_cast<const float4*>(Ssh + plocal * ASTR + kl);
                float4 x1 = *reinterpret_cast<const float4*>(Ssh + plocal * ASTR + 64 + kl);
                float c0 = Uc2[g * 2], c1 = Uc2[g * 2 + 1];
                float4 o;
                o.x = fmaf(c1, x1.x, c0 * x0.x);
                o.y = fmaf(c1, x1.y, c0 * x0.y);
                o.z = fmaf(c1, x1.z, c0 * x0.z);
                o.w = fmaf(c1, x1.w, c0 * x0.w);
                *reinterpret_cast<float4*>(
                    Y + (size_t)(chunk * 128 + plocal) * 256 + g * 64 + kl) = o;
            }
        }
        if (chunk == 0) __syncthreads();   // protect A2 scratch before chunk-1 rewrites it
    }
}

extern "C" void kernel_launch(void* const* d_in, const int* in_sizes, int n_in,
                              void* d_out, int out_size)
{
    const float* rho = (const float*)d_in[0];
    const float* ux  = (const float*)d_in[1];
    const float* uy  = (const float*)d_in[2];
    const float* uc  = (const float*)d_in[3];
    float* out = (float*)d_out;

    const int nb = in_sizes[0] / (QK * QK);   // 256 batches

    cudaFuncSetAttribute(qconv_kernel,
                         cudaFuncAttributeMaxDynamicSharedMemorySize, SMEM_BYTES);
    qconv_kernel<<<nb, 256, SMEM_BYTES>>>(rho, ux, uy, uc, out);
}

// round 8
// speedup vs baseline: 1.1530x; 1.1530x over previous
#include <cuda_runtime.h>

// QConv2d: new_rho[b] = V * rho[b] * V^T,  V = kron(uc[:,2:4], ux, uy) (256x128).
// Channel insertion is a pure +128 index shift, so only the right 128 columns
// of U matter. Factorize:
//   M2 = (I2 (x) ux (x) uy) rho (I2 (x) ux (x) uy)^T   -- in-place, 68 KB smem
//   out block (g,g') = sum_{f,f'} c[g,f] c[g',f'] * M2 block (f,f')
// One CTA per batch, 256 threads, single wave (2 CTAs/SM).

#define SSTR 132   // buffer row stride: float4 accesses conflict-free (132%32=4)

static constexpr int UY_OFF      = 128 * SSTR;
static constexpr int UX_OFF      = UY_OFF + 64;
static constexpr int UC_OFF      = UX_OFF + 64;
static constexpr int SMEM_FLOATS = UC_OFF + 8;
static constexpr int SMEM_BYTES  = SMEM_FLOATS * 4;   // 68,128 B

__global__ void __launch_bounds__(256, 2)
qconv_kernel(const float* __restrict__ rho_g,
             const float* __restrict__ ux_g,
             const float* __restrict__ uy_g,
             const float* __restrict__ uc_g,
             float* __restrict__ out_g)
{
    extern __shared__ float sm[];
    float* __restrict__ Ssh = sm;             // [128][SSTR] : rho -> M1 -> M2
    float* __restrict__ Uy  = sm + UY_OFF;
    float* __restrict__ Ux  = sm + UX_OFF;
    float* __restrict__ Uc2 = sm + UC_OFF;    // Uc2[g*2+f] = uc[g][2+f]

    const int tid = threadIdx.x;
    const int b   = blockIdx.x;

    if (tid < 64) {
        Uy[tid] = uy_g[tid];
        Ux[tid] = ux_g[tid];
    } else if (tid < 72) {
        int t = tid - 64;
        Uc2[t] = uc_g[(t >> 1) * 4 + 2 + (t & 1)];
    }

    // Load rho[b] (128x128 fp32), float4 coalesced, into strided buffer.
    {
        const float4* __restrict__ src =
            reinterpret_cast<const float4*>(rho_g) + (size_t)b * 4096;
        #pragma unroll
        for (int it = 0; it < 16; it++) {
            int idx = tid + it * 256;
            int row = idx >> 5;
            int c4  = idx & 31;
            *reinterpret_cast<float4*>(Ssh + row * SSTR + c4 * 4) = src[idx];
        }
    }
    __syncthreads();

    const int fh   = tid >> 7;      // which f (or f') half this thread owns
    const int lane = tid & 127;     // column r (stage 1) / row m (stage 2)

    // ---------- Stage 1: left transform (ux (x) uy) per column, in place ----------
    // Thread owns half-column {rows fh*64..fh*64+63, col=lane}. Scalar LDS/STS:
    // consecutive lanes -> consecutive banks, conflict-free.
    {
        float* col = Ssh + (fh * 64) * SSTR + lane;

        // Y pass: within each 8-group i, a[l] = sum_j Uy[l][j] v[j]
        #pragma unroll
        for (int i = 0; i < 8; i++) {
            float v[8];
            #pragma unroll
            for (int j = 0; j < 8; j++) v[j] = col[(i * 8 + j) * SSTR];
            #pragma unroll
            for (int l = 0; l < 8; l++) {
                float acc = Uy[l * 8] * v[0];
                #pragma unroll
                for (int j = 1; j < 8; j++) acc = fmaf(Uy[l * 8 + j], v[j], acc);
                col[(i * 8 + l) * SSTR] = acc;
            }
        }
        // X pass: for fixed l, o[k] = sum_i Ux[k][i] t[i]; read/write sets match per l.
        #pragma unroll
        for (int l = 0; l < 8; l++) {
            float t[8];
            #pragma unroll
            for (int i = 0; i < 8; i++) t[i] = col[(i * 8 + l) * SSTR];
            #pragma unroll
            for (int k = 0; k < 8; k++) {
                float acc = Ux[k * 8] * t[0];
                #pragma unroll
                for (int i = 1; i < 8; i++) acc = fmaf(Ux[k * 8 + i], t[i], acc);
                col[(k * 8 + l) * SSTR] = acc;
            }
        }
    }
    __syncthreads();

    // ---------- Stage 2: right transform per row, in place, float4 accesses ----------
    // Thread owns half-row {row=lane, cols fh*64..fh*64+63}. All LDS/STS are
    // 128-bit: stride-132 rows are conflict-free in 8-lane phases.
    {
        float* rowp = Ssh + lane * SSTR + fh * 64;

        // Y pass
        #pragma unroll
        for (int i = 0; i < 8; i++) {
            float4 va = *reinterpret_cast<const float4*>(rowp + i * 8);
            float4 vb = *reinterpret_cast<const float4*>(rowp + i * 8 + 4);
            float v[8] = {va.x, va.y, va.z, va.w, vb.x, vb.y, vb.z, vb.w};
            float a[8];
            #pragma unroll
            for (int l = 0; l < 8; l++) {
                float acc = Uy[l * 8] * v[0];
                #pragma unroll
                for (int j = 1; j < 8; j++) acc = fmaf(Uy[l * 8 + j], v[j], acc);
                a[l] = acc;
            }
            *reinterpret_cast<float4*>(rowp + i * 8)     = make_float4(a[0], a[1], a[2], a[3]);
            *reinterpret_cast<float4*>(rowp + i * 8 + 4) = make_float4(a[4], a[5], a[6], a[7]);
        }
        // X pass on float4 l-quads: load all t[i] first, then overwrite.
        #pragma unroll
        for (int lq = 0; lq < 2; lq++) {
            float4 t[8];
            #pragma unroll
            for (int i = 0; i < 8; i++)
                t[i] = *reinterpret_cast<const float4*>(rowp + i * 8 + lq * 4);
            #pragma unroll
            for (int k = 0; k < 8; k++) {
                float u0 = Ux[k * 8];
                float4 o;
                o.x = u0 * t[0].x; o.y = u0 * t[0].y; o.z = u0 * t[0].z; o.w = u0 * t[0].w;
                #pragma unroll
                for (int i = 1; i < 8; i++) {
                    float u = Ux[k * 8 + i];
                    o.x = fmaf(u, t[i].x, o.x);
                    o.y = fmaf(u, t[i].y, o.y);
                    o.z = fmaf(u, t[i].z, o.z);
                    o.w = fmaf(u, t[i].w, o.w);
                }
                *reinterpret_cast<float4*>(rowp + k * 8 + lq * 4) = o;
            }
        }
    }
    __syncthreads();

    // ---------- Combine: each M2 float4 read once, fan out to 16 output blocks ----------
    {
        float c[8];
        #pragma unroll
        for (int q = 0; q < 8; q++) c[q] = Uc2[q];

        float* __restrict__ Y = out_g + (size_t)b * 65536;

        #pragma unroll
        for (int it = 0; it < 4; it++) {
            int idx = tid + it * 256;          // 1024 (kl, s4) positions
            int s4  = idx & 15;                // float4 index within 64-col block
            int kl  = idx >> 4;                // row within block

            const float* p0 = Ssh + kl * SSTR + s4 * 4;          // f = 0 row
            const float* p1 = Ssh + (64 + kl) * SSTR + s4 * 4;   // f = 1 row
            float4 x00 = *reinterpret_cast<const float4*>(p0);        // f=0,f'=0
            float4 x01 = *reinterpret_cast<const float4*>(p0 + 64);   // f=0,f'=1
            float4 x10 = *reinterpret_cast<const float4*>(p1);        // f=1,f'=0
            float4 x11 = *reinterpret_cast<const float4*>(p1 + 64);   // f=1,f'=1

            #pragma unroll
            for (int g = 0; g < 4; g++) {
                float g0 = c[g * 2], g1 = c[g * 2 + 1];
                float4 e0, e1;                        // combine over f
                e0.x = fmaf(g1, x10.x, g0 * x00.x);
                e0.y = fmaf(g1, x10.y, g0 * x00.y);
                e0.z = fmaf(g1, x10.z, g0 * x00.z);
                e0.w = fmaf(g1, x10.w, g0 * x00.w);
                e1.x = fmaf(g1, x11.x, g0 * x01.x);
                e1.y = fmaf(g1, x11.y, g0 * x01.y);
                e1.z = fmaf(g1, x11.z, g0 * x01.z);
                e1.w = fmaf(g1, x11.w, g0 * x01.w);
                #pragma unroll
                for (int gp = 0; gp < 4; gp++) {
                    float d0 = c[gp * 2], d1 = c[gp * 2 + 1];
                    float4 o;                         // combine over f'
                    o.x = fmaf(d1, e1.x, d0 * e0.x);
                    o.y = fmaf(d1, e1.y, d0 * e0.y);
                    o.z = fmaf(d1, e1.z, d0 * e0.z);
                    o.w = fmaf(d1, e1.w, d0 * e0.w);
                    *reinterpret_cast<float4*>(
                        Y + (size_t)(g * 64 + kl) * 256 + gp * 64 + s4 * 4) = o;
                }
            }
        }
    }
}

extern "C" void kernel_launch(void* const* d_in, const int* in_sizes, int n_in,
                              void* d_out, int out_size)
{
    const float* rho = (const float*)d_in[0];
    const float* ux  = (const float*)d_in[1];
    const float* uy  = (const float*)d_in[2];
    const float* uc  = (const float*)d_in[3];
    float* out = (float*)d_out;

    const int nb = in_sizes[0] / (128 * 128);   // 256 batches

    cudaFuncSetAttribute(qconv_kernel,
                         cudaFuncAttributeMaxDynamicSharedMemorySize, SMEM_BYTES);
    qconv_kernel<<<nb, 256, SMEM_BYTES>>>(rho, ux, uy, uc, out);
}

// round 9
// speedup vs baseline: 1.1648x; 1.0102x over previous
#include <cuda_runtime.h>

// QConv2d: new_rho[b] = V * rho[b] * V^T,  V = kron(uc[:,2:4], ux, uy) (256x128).
// Channel insertion is a pure +128 index shift. Factorization:
//   M2 = (I2 (x) ux (x) uy) rho (I2 (x) ux (x) uy)^T   -- in-place, 68 KB smem
//   out block (g,g') = sum_{f,f'} c[g,f] c[g',f'] * M2 block (f,f')
// One CTA per batch, 512 threads, 2 CTAs/SM (32 warps/SM), single wave.

#define SSTR 132   // buffer row stride: float4 accesses conflict-free (132%32=4)

static constexpr int UY_OFF      = 128 * SSTR;
static constexpr int UX_OFF      = UY_OFF + 64;
static constexpr int UC_OFF      = UX_OFF + 64;
static constexpr int SMEM_FLOATS = UC_OFF + 8;
static constexpr int SMEM_BYTES  = SMEM_FLOATS * 4;   // 68,128 B

__global__ void __launch_bounds__(512, 2)
qconv_kernel(const float* __restrict__ rho_g,
             const float* __restrict__ ux_g,
             const float* __restrict__ uy_g,
             const float* __restrict__ uc_g,
             float* __restrict__ out_g)
{
    extern __shared__ float sm[];
    float* __restrict__ Ssh = sm;             // [128][SSTR] : rho -> M1 -> M2
    float* __restrict__ Uy  = sm + UY_OFF;
    float* __restrict__ Ux  = sm + UX_OFF;
    float* __restrict__ Uc2 = sm + UC_OFF;    // Uc2[g*2+f] = uc[g][2+f]

    const int tid = threadIdx.x;
    const int b   = blockIdx.x;

    if (tid < 64) {
        Uy[tid] = uy_g[tid];
        Ux[tid] = ux_g[tid];
    } else if (tid < 72) {
        int t = tid - 64;
        Uc2[t] = uc_g[(t >> 1) * 4 + 2 + (t & 1)];
    }

    // Load rho[b] (128x128 fp32), float4 coalesced, into strided buffer.
    {
        const float4* __restrict__ src =
            reinterpret_cast<const float4*>(rho_g) + (size_t)b * 4096;
        #pragma unroll
        for (int it = 0; it < 8; it++) {
            int idx = tid + it * 512;
            int row = idx >> 5;
            int c4  = idx & 31;
            *reinterpret_cast<float4*>(Ssh + row * SSTR + c4 * 4) = src[idx];
        }
    }
    __syncthreads();

    const int lane = tid & 127;         // column r (stage 1) / row m (stage 2)
    const int fh   = (tid >> 7) & 1;    // f (or f') half — warp-uniform
    const int sub  = tid >> 8;          // sibling split — warp-uniform

    // ---------- Stage 1: left transform (ux (x) uy) per column, in place ----------
    // Half-column {rows fh*64..+63, col=lane} shared by 2 sibling threads.
    {
        float* col = Ssh + (fh * 64) * SSTR + lane;

        // Y pass: sibling owns i-groups sub*4..sub*4+3 (disjoint rows, in-place safe)
        #pragma unroll
        for (int ii = 0; ii < 4; ii++) {
            int i = sub * 4 + ii;
            float v[8];
            #pragma unroll
            for (int j = 0; j < 8; j++) v[j] = col[(i * 8 + j) * SSTR];
            #pragma unroll
            for (int l = 0; l < 8; l++) {
                float acc = Uy[l * 8] * v[0];
                #pragma unroll
                for (int j = 1; j < 8; j++) acc = fmaf(Uy[l * 8 + j], v[j], acc);
                col[(i * 8 + l) * SSTR] = acc;
            }
        }
        __syncthreads();

        // X pass: sibling owns l = sub*4..sub*4+3 (positions (i*8+l) disjoint per l)
        #pragma unroll
        for (int ll = 0; ll < 4; ll++) {
            int l = sub * 4 + ll;
            float t[8];
            #pragma unroll
            for (int i = 0; i < 8; i++) t[i] = col[(i * 8 + l) * SSTR];
            #pragma unroll
            for (int k = 0; k < 8; k++) {
                float acc = Ux[k * 8] * t[0];
                #pragma unroll
                for (int i = 1; i < 8; i++) acc = fmaf(Ux[k * 8 + i], t[i], acc);
                col[(k * 8 + l) * SSTR] = acc;
            }
        }
    }
    __syncthreads();

    // ---------- Stage 2: right transform per row, in place, float4 accesses ----------
    // Half-row {row=lane, cols fh*64..+63} shared by 2 sibling threads.
    {
        float* rowp = Ssh + lane * SSTR + fh * 64;

        // Y pass: sibling owns i-groups sub*4..sub*4+3
        #pragma unroll
        for (int ii = 0; ii < 4; ii++) {
            int i = sub * 4 + ii;
            float4 va = *reinterpret_cast<const float4*>(rowp + i * 8);
            float4 vb = *reinterpret_cast<const float4*>(rowp + i * 8 + 4);
            float v[8] = {va.x, va.y, va.z, va.w, vb.x, vb.y, vb.z, vb.w};
            float a[8];
            #pragma unroll
            for (int l = 0; l < 8; l++) {
                float acc = Uy[l * 8] * v[0];
                #pragma unroll
                for (int j = 1; j < 8; j++) acc = fmaf(Uy[l * 8 + j], v[j], acc);
                a[l] = acc;
            }
            *reinterpret_cast<float4*>(rowp + i * 8)     = make_float4(a[0], a[1], a[2], a[3]);
            *reinterpret_cast<float4*>(rowp + i * 8 + 4) = make_float4(a[4], a[5], a[6], a[7]);
        }
        __syncthreads();

        // X pass: sibling owns l-quad lq = sub (columns i*8 + sub*4 .. +3)
        {
            const int lq = sub;
            float4 t[8];
            #pragma unroll
            for (int i = 0; i < 8; i++)
                t[i] = *reinterpret_cast<const float4*>(rowp + i * 8 + lq * 4);
            #pragma unroll
            for (int k = 0; k < 8; k++) {
                float u0 = Ux[k * 8];
                float4 o;
                o.x = u0 * t[0].x; o.y = u0 * t[0].y; o.z = u0 * t[0].z; o.w = u0 * t[0].w;
                #pragma unroll
                for (int i = 1; i < 8; i++) {
                    float u = Ux[k * 8 + i];
                    o.x = fmaf(u, t[i].x, o.x);
                    o.y = fmaf(u, t[i].y, o.y);
                    o.z = fmaf(u, t[i].z, o.z);
                    o.w = fmaf(u, t[i].w, o.w);
                }
                *reinterpret_cast<float4*>(rowp + k * 8 + lq * 4) = o;
            }
        }
    }
    __syncthreads();

    // ---------- Combine: each M2 float4 read once, fan out to 16 output blocks ----------
    {
        float c[8];
        #pragma unroll
        for (int q = 0; q < 8; q++) c[q] = Uc2[q];

        float* __restrict__ Y = out_g + (size_t)b * 65536;

        #pragma unroll
        for (int it = 0; it < 2; it++) {
            int idx = tid + it * 512;          // 1024 (kl, s4) positions
            int s4  = idx & 15;                // float4 index within 64-col block
            int kl  = idx >> 4;                // row within block

            const float* p0 = Ssh + kl * SSTR + s4 * 4;          // f = 0 row
            const float* p1 = Ssh + (64 + kl) * SSTR + s4 * 4;   // f = 1 row
            float4 x00 = *reinterpret_cast<const float4*>(p0);        // f=0,f'=0
            float4 x01 = *reinterpret_cast<const float4*>(p0 + 64);   // f=0,f'=1
            float4 x10 = *reinterpret_cast<const float4*>(p1);        // f=1,f'=0
            float4 x11 = *reinterpret_cast<const float4*>(p1 + 64);   // f=1,f'=1

            #pragma unroll
            for (int g = 0; g < 4; g++) {
                float g0 = c[g * 2], g1 = c[g * 2 + 1];
                float4 e0, e1;                        // combine over f
                e0.x = fmaf(g1, x10.x, g0 * x00.x);
                e0.y = fmaf(g1, x10.y, g0 * x00.y);
                e0.z = fmaf(g1, x10.z, g0 * x00.z);
                e0.w = fmaf(g1, x10.w, g0 * x00.w);
                e1.x = fmaf(g1, x11.x, g0 * x01.x);
                e1.y = fmaf(g1, x11.y, g0 * x01.y);
                e1.z = fmaf(g1, x11.z, g0 * x01.z);
                e1.w = fmaf(g1, x11.w, g0 * x01.w);
                #pragma unroll
                for (int gp = 0; gp < 4; gp++) {
                    float d0 = c[gp * 2], d1 = c[gp * 2 + 1];
                    float4 o;                         // combine over f'
                    o.x = fmaf(d1, e1.x, d0 * e0.x);
                    o.y = fmaf(d1, e1.y, d0 * e0.y);
                    o.z = fmaf(d1, e1.z, d0 * e0.z);
                    o.w = fmaf(d1, e1.w, d0 * e0.w);
                    *reinterpret_cast<float4*>(
                        Y + (size_t)(g * 64 + kl) * 256 + gp * 64 + s4 * 4) = o;
                }
            }
        }
    }
}

extern "C" void kernel_launch(void* const* d_in, const int* in_sizes, int n_in,
                              void* d_out, int out_size)
{
    const float* rho = (const float*)d_in[0];
    const float* ux  = (const float*)d_in[1];
    const float* uy  = (const float*)d_in[2];
    const float* uc  = (const float*)d_in[3];
    float* out = (float*)d_out;

    const int nb = in_sizes[0] / (128 * 128);   // 256 batches

    cudaFuncSetAttribute(qconv_kernel,
                         cudaFuncAttributeMaxDynamicSharedMemorySize, SMEM_BYTES);
    qconv_kernel<<<nb, 512, SMEM_BYTES>>>(rho, ux, uy, uc, out);
}